// round 3
// baseline (speedup 1.0000x reference)
#include <cuda_runtime.h>
#include <cstdint>

#define N_    32
#define CIN_  64
#define COUT_ 64
#define T_    6
#define V_    512
#define M_    (COUT_ * T_)      // 384 rows of the big GEMM (c*6+t)
#define NEG_FILL -1000.0f
#define SLOPE 0.2f

// Scratch (allocation-free rule: __device__ globals)
__device__ float g_xc[N_ * M_ * V_];   // xc[n][c][t][v]  (25 MB)
__device__ float g_si[N_ * V_];
__device__ float g_sj[N_ * V_];

// ---------------------------------------------------------------------------
// Kernel A: xc[n,c,t,v] = sum_i conv_w[c,i] * x[n,i,t,v] + conv_b[c]
// Block = one (n, t, 128-wide v tile). 256 threads, 8c x 4v register tile.
// ---------------------------------------------------------------------------
__global__ __launch_bounds__(256) void k_conv(const float* __restrict__ x,
                                              const float* __restrict__ w,
                                              const float* __restrict__ b) {
    __shared__ float xs[64][128];   // [i][v]   32 KB
    __shared__ float ws[64][64];    // [c][i]   16 KB
    const int n = blockIdx.z, t = blockIdx.y, bv = blockIdx.x * 128;
    const int tid = threadIdx.x;

#pragma unroll
    for (int r = 0; r < 4; ++r) {
        int f = tid + r * 256;
        int row = f >> 4, c4 = (f & 15) << 2;
        *(float4*)&ws[row][c4] = *(const float4*)(w + row * 64 + c4);
    }
#pragma unroll
    for (int r = 0; r < 8; ++r) {
        int f = tid + r * 256;
        int row = f >> 5, c4 = (f & 31) << 2;
        *(float4*)&xs[row][c4] =
            *(const float4*)(x + (((size_t)n * CIN_ + row) * T_ + t) * V_ + bv + c4);
    }
    __syncthreads();

    const int tx = tid & 31;   // v group (4 v's)
    const int ty = tid >> 5;   // c group (8 c's)
    float acc[8][4];
#pragma unroll
    for (int i = 0; i < 8; ++i)
#pragma unroll
        for (int j = 0; j < 4; ++j) acc[i][j] = 0.f;

#pragma unroll 4
    for (int kk = 0; kk < 64; ++kk) {
        float4 bx = *(float4*)&xs[kk][tx << 2];
#pragma unroll
        for (int cc = 0; cc < 8; ++cc) {
            float a = ws[ty * 8 + cc][kk];
            acc[cc][0] = fmaf(a, bx.x, acc[cc][0]);
            acc[cc][1] = fmaf(a, bx.y, acc[cc][1]);
            acc[cc][2] = fmaf(a, bx.z, acc[cc][2]);
            acc[cc][3] = fmaf(a, bx.w, acc[cc][3]);
        }
    }
#pragma unroll
    for (int cc = 0; cc < 8; ++cc) {
        int c = ty * 8 + cc;
        float bias = b[c];
        float4 o = make_float4(acc[cc][0] + bias, acc[cc][1] + bias,
                               acc[cc][2] + bias, acc[cc][3] + bias);
        *(float4*)(g_xc + (((size_t)n * COUT_ + c) * T_ + t) * V_ + bv + (tx << 2)) = o;
    }
}

// ---------------------------------------------------------------------------
// Kernel B: folded attention-score projections. One block per n, thread = v.
// ---------------------------------------------------------------------------
__global__ __launch_bounds__(512) void k_scores(const float* __restrict__ l1_w,
                                                const float* __restrict__ l2_w,
                                                const float* __restrict__ l2_b) {
    const int n = blockIdx.x, v = threadIdx.x;
    __shared__ float cs[M_], cd[M_];
    if (v < M_) {
        int c = v / T_, t = v % T_;
        float lw = l2_w[t];
        cs[v] = lw * l1_w[c];
        cd[v] = lw * l1_w[COUT_ + c];
    }
    __syncthreads();

    float si = 0.f, sj = 0.f;
    const float* xp = g_xc + (size_t)n * M_ * V_ + v;
#pragma unroll 8
    for (int m = 0; m < M_; ++m) {
        float xv = xp[(size_t)m * V_];
        si = fmaf(xv, cs[m], si);
        sj = fmaf(xv, cd[m], sj);
    }
    float ss = 0.f, sd = 0.f;
#pragma unroll
    for (int c = 0; c < COUT_; ++c) { ss += l1_w[c]; sd += l1_w[COUT_ + c]; }
    float lb = l2_b[0];
    g_si[n * V_ + v] = si + lb * ss;
    g_sj[n * V_ + v] = sj + lb * sd;
}

// ---------------------------------------------------------------------------
// Kernel C: per (n,v) row: leaky_relu(s_i+s_j+b), mask fill -1000, softmax.
// ---------------------------------------------------------------------------
__global__ __launch_bounds__(256) void k_softmax(const float* __restrict__ A,
                                                 const float* __restrict__ l1_b,
                                                 float* __restrict__ a4) {
    const int v = blockIdx.x, n = blockIdx.y, tid = threadIdx.x;
    __shared__ float red[256];

    const float siv = g_si[n * V_ + v] + l1_b[0];
    const float* mrow = A + (((size_t)n * 8 + 7) * V_ + v) * V_;
    const float* sjn = g_sj + n * V_;

    float vals[2];
#pragma unroll
    for (int r = 0; r < 2; ++r) {
        int w = tid + r * 256;
        float sc = siv + sjn[w];
        float a1 = sc >= 0.f ? sc : SLOPE * sc;
        float mk = mrow[w];
        vals[r] = (mk == 0.f) ? NEG_FILL : a1;
    }

    red[tid] = fmaxf(vals[0], vals[1]);
    __syncthreads();
#pragma unroll
    for (int s = 128; s > 0; s >>= 1) {
        if (tid < s) red[tid] = fmaxf(red[tid], red[tid + s]);
        __syncthreads();
    }
    float mx = red[0];
    __syncthreads();

    float e0 = __expf(vals[0] - mx);
    float e1 = __expf(vals[1] - mx);
    red[tid] = e0 + e1;
    __syncthreads();
#pragma unroll
    for (int s = 128; s > 0; s >>= 1) {
        if (tid < s) red[tid] += red[tid + s];
        __syncthreads();
    }
    float inv = 1.0f / red[0];

    float* orow = a4 + ((size_t)n * V_ + v) * V_;
    orow[tid] = e0 * inv;
    orow[tid + 256] = e1 * inv;
}

// ---------------------------------------------------------------------------
// Kernel D: out[n] (384x512) = xc[n] (384x512) @ a4[n] (512x512)
// 128x128x8 smem-tiled SGEMM, 256 threads, 8x8 microtile, DOUBLE-BUFFERED:
// one barrier per K-tile, next tile staged through registers during compute.
// ---------------------------------------------------------------------------
__global__ __launch_bounds__(256) void k_gemm(const float* __restrict__ A4,
                                              float* __restrict__ OUT) {
    const int n = blockIdx.z;
    const float* Ap = g_xc + (size_t)n * M_ * V_;        // [384][512]
    const float* Bp = A4 + (size_t)n * V_ * V_;          // [512][512]
    float* Cp = OUT + (size_t)n * M_ * V_;

    const int bm = blockIdx.y * 128, bn = blockIdx.x * 128;
    const int tid = threadIdx.x;

    __shared__ float As[2][8][128];   // transposed A tile, 2 buffers
    __shared__ float Bs[2][8][128];

    const int a_row = tid >> 1, a_col = (tid & 1) * 4;   // 128x8 tile
    const int b_row = tid >> 5, b_col = (tid & 31) * 4;  // 8x128 tile
    const int tx = tid & 15, ty = tid >> 4;

    const float* ApT = Ap + (size_t)(bm + a_row) * V_ + a_col;
    const float* BpT = Bp + (size_t)b_row * V_ + bn + b_col;

    float acc[8][8];
#pragma unroll
    for (int i = 0; i < 8; ++i)
#pragma unroll
        for (int j = 0; j < 8; ++j) acc[i][j] = 0.f;

    // preload tile 0 into buffer 0
    {
        float4 av = *(const float4*)(ApT);
        As[0][a_col + 0][a_row] = av.x;
        As[0][a_col + 1][a_row] = av.y;
        As[0][a_col + 2][a_row] = av.z;
        As[0][a_col + 3][a_row] = av.w;
        *(float4*)&Bs[0][b_row][b_col] = *(const float4*)(BpT);
    }
    __syncthreads();

    int cur = 0;
    for (int k0 = 0; k0 < V_; k0 += 8) {
        float4 av, bv;
        const bool more = (k0 + 8) < V_;
        if (more) {
            av = *(const float4*)(ApT + k0 + 8);
            bv = *(const float4*)(BpT + (size_t)(k0 + 8) * V_);
        }

#pragma unroll
        for (int k = 0; k < 8; ++k) {
            float4 a0 = *(float4*)&As[cur][k][ty * 8];
            float4 a1 = *(float4*)&As[cur][k][ty * 8 + 4];
            float4 b0 = *(float4*)&Bs[cur][k][tx * 8];
            float4 b1 = *(float4*)&Bs[cur][k][tx * 8 + 4];
            float a[8] = {a0.x, a0.y, a0.z, a0.w, a1.x, a1.y, a1.z, a1.w};
            float b[8] = {b0.x, b0.y, b0.z, b0.w, b1.x, b1.y, b1.z, b1.w};
#pragma unroll
            for (int i = 0; i < 8; ++i)
#pragma unroll
                for (int j = 0; j < 8; ++j)
                    acc[i][j] = fmaf(a[i], b[j], acc[i][j]);
        }

        if (more) {
            int nxt = cur ^ 1;
            As[nxt][a_col + 0][a_row] = av.x;
            As[nxt][a_col + 1][a_row] = av.y;
            As[nxt][a_col + 2][a_row] = av.z;
            As[nxt][a_col + 3][a_row] = av.w;
            *(float4*)&Bs[nxt][b_row][b_col] = bv;
            __syncthreads();
        }
        cur ^= 1;
    }

#pragma unroll
    for (int i = 0; i < 8; ++i) {
        float* cp = Cp + (size_t)(bm + ty * 8 + i) * V_ + bn + tx * 8;
        float4 o0 = make_float4(acc[i][0], acc[i][1], acc[i][2], acc[i][3]);
        float4 o1 = make_float4(acc[i][4], acc[i][5], acc[i][6], acc[i][7]);
        *(float4*)cp = o0;
        *(float4*)(cp + 4) = o1;
    }
}

// ---------------------------------------------------------------------------
extern "C" void kernel_launch(void* const* d_in, const int* in_sizes, int n_in,
                              void* d_out, int out_size) {
    const float* x      = (const float*)d_in[0];
    const float* A      = (const float*)d_in[1];
    const float* conv_w = (const float*)d_in[2];
    const float* conv_b = (const float*)d_in[3];
    const float* l1_w   = (const float*)d_in[4];
    const float* l1_b   = (const float*)d_in[5];
    const float* l2_w   = (const float*)d_in[6];
    const float* l2_b   = (const float*)d_in[7];

    float* out = (float*)d_out;                       // (32,64,6,512)
    float* a4  = out + (size_t)N_ * COUT_ * T_ * V_;  // (32,1,512,512)

    k_conv<<<dim3(V_ / 128, T_, N_), 256>>>(x, conv_w, conv_b);
    k_scores<<<N_, V_>>>(l1_w, l2_w, l2_b);
    k_softmax<<<dim3(V_, N_), 256>>>(A, l1_b, a4);
    k_gemm<<<dim3(V_ / 128, M_ / 128, N_), 256>>>(a4, out);
}